// round 12
// baseline (speedup 1.0000x reference)
#include <cuda_runtime.h>
#include <cuda_fp16.h>
#include <cstdint>
#include <cstddef>

// Problem constants
#define N_Q   8192
#define M_KV  8192
#define QDIM  256
#define MID   128
#define DV    256
#define BM    64
#define BN    64
#define NIT   (M_KV / BN)   // 128
// exp folded to ex2: e^(s*SCALE - SHIFT) = 2^(s*SC2 - SH2)
#define SC2 (0.08838834764831845f * 1.4426950408889634f)
#define SH2 (8.0f * 1.4426950408889634f)

// Scratch (device globals; no allocation allowed)
__device__ __half g_Q[N_Q * MID];      // fp16 Q  [8192][128]
__device__ __half g_K[M_KV * MID];     // fp16 K  [8192][128]
__device__ __half g_Vt[DV * M_KV];     // fp16 V^T [256][8192]

// ---------------- smem geometry for flash kernel (bytes) ----------------
#define LDQ 136
#define LDK 136
#define LDV 72
#define OFF_Q  0
#define OFF_K0 17408
#define OFF_K1 34816
#define OFF_V0 52224
#define OFF_V1 89088
#define SMEM_BYTES 125952
#define SO_LD 260        // float stride for O-partial exchange [64][260]

// ---------------- helpers ----------------
__device__ __forceinline__ void cpa16(void* dst, const void* src) {
    unsigned s = (unsigned)__cvta_generic_to_shared(dst);
    asm volatile("cp.async.cg.shared.global [%0], [%1], 16;\n" :: "r"(s), "l"(src));
}
#define CP_COMMIT asm volatile("cp.async.commit_group;\n" ::)
#define CP_WAIT1  asm volatile("cp.async.wait_group 1;\n" ::)
#define CP_WAIT0  asm volatile("cp.async.wait_group 0;\n" ::)

__device__ __forceinline__ void mma16816(float c[4],
                                         unsigned a0, unsigned a1, unsigned a2, unsigned a3,
                                         unsigned b0, unsigned b1) {
    asm volatile(
        "mma.sync.aligned.m16n8k16.row.col.f32.f16.f16.f32 "
        "{%0,%1,%2,%3}, {%4,%5,%6,%7}, {%8,%9}, {%0,%1,%2,%3};\n"
        : "+f"(c[0]), "+f"(c[1]), "+f"(c[2]), "+f"(c[3])
        : "r"(a0), "r"(a1), "r"(a2), "r"(a3), "r"(b0), "r"(b1));
}

__device__ __forceinline__ unsigned pack2(float a, float b) {
    __half2 h = __floats2half2_rn(a, b);
    return *reinterpret_cast<unsigned*>(&h);
}

__device__ __forceinline__ float ex2f(float x) {
    float y;
    asm("ex2.approx.f32 %0, %1;" : "=f"(y) : "f"(x));
    return y;
}

// ---------------- kernel 1: projections via split-fp16 tensor cores ----------------
#define LDP 40   // smem row stride in halves (80B): conflict-free fragment loads
__global__ __launch_bounds__(256) void projmma_kernel(const float* __restrict__ Xq,
                                                      const float* __restrict__ Xk,
                                                      const float* __restrict__ Wq,
                                                      const float* __restrict__ bq,
                                                      const float* __restrict__ Wk,
                                                      const float* __restrict__ bk) {
    __shared__ __half Xh[128 * LDP], Xl[128 * LDP], Wh[128 * LDP], Wl[128 * LDP];
    const int b = blockIdx.x;
    const int which = b >> 6;
    const int row0 = (b & 63) * 128;
    const float* X    = which ? Xk : Xq;
    const float* W    = which ? Wk : Wq;
    const float* bias = which ? bk : bq;

    const int tid  = threadIdx.x;
    const int lane = tid & 31;
    const int warp = tid >> 5;
    const int r0   = lane >> 2;
    const int cq   = lane & 3;

    const int srow  = tid >> 1;
    const int scol  = (tid & 1) * 16;

    float acc[16][4];
#pragma unroll
    for (int nb = 0; nb < 16; nb++)
#pragma unroll
        for (int i = 0; i < 4; i++) acc[nb][i] = 0.f;

    float4 xr[4], wr[4];
#pragma unroll
    for (int j = 0; j < 4; j++) {
        xr[j] = *(const float4*)(X + (size_t)(row0 + srow) * QDIM + scol + 4 * j);
        wr[j] = *(const float4*)(W + (size_t)srow * QDIM + scol + 4 * j);
    }

    for (int chunk = 0; chunk < 8; chunk++) {
        __syncthreads();
#pragma unroll
        for (int j = 0; j < 4; j++) {
            const float xv[4] = {xr[j].x, xr[j].y, xr[j].z, xr[j].w};
            const float wv[4] = {wr[j].x, wr[j].y, wr[j].z, wr[j].w};
#pragma unroll
            for (int e = 0; e < 2; e++) {
                int c = scol + 4 * j + 2 * e;
                __half h0 = __float2half_rn(xv[2 * e]);
                __half h1 = __float2half_rn(xv[2 * e + 1]);
                __half l0 = __float2half_rn(xv[2 * e]     - __half2float(h0));
                __half l1 = __float2half_rn(xv[2 * e + 1] - __half2float(h1));
                *(__half2*)&Xh[srow * LDP + c] = __halves2half2(h0, h1);
                *(__half2*)&Xl[srow * LDP + c] = __halves2half2(l0, l1);
                __half g0 = __float2half_rn(wv[2 * e]);
                __half g1 = __float2half_rn(wv[2 * e + 1]);
                __half m0 = __float2half_rn(wv[2 * e]     - __half2float(g0));
                __half m1 = __float2half_rn(wv[2 * e + 1] - __half2float(g1));
                *(__half2*)&Wh[srow * LDP + c] = __halves2half2(g0, g1);
                *(__half2*)&Wl[srow * LDP + c] = __halves2half2(m0, m1);
            }
        }
        __syncthreads();
        if (chunk + 1 < 8) {
            int k0 = (chunk + 1) * 32;
#pragma unroll
            for (int j = 0; j < 4; j++) {
                xr[j] = *(const float4*)(X + (size_t)(row0 + srow) * QDIM + k0 + scol + 4 * j);
                wr[j] = *(const float4*)(W + (size_t)srow * QDIM + k0 + scol + 4 * j);
            }
        }
#pragma unroll
        for (int ks = 0; ks < 2; ks++) {
            const __half* xp = Xh + (warp * 16 + r0) * LDP + ks * 16 + cq * 2;
            unsigned ah0 = *(const unsigned*)xp;
            unsigned ah1 = *(const unsigned*)(xp + 8 * LDP);
            unsigned ah2 = *(const unsigned*)(xp + 8);
            unsigned ah3 = *(const unsigned*)(xp + 8 * LDP + 8);
            const __half* xq2 = Xl + (warp * 16 + r0) * LDP + ks * 16 + cq * 2;
            unsigned al0 = *(const unsigned*)xq2;
            unsigned al1 = *(const unsigned*)(xq2 + 8 * LDP);
            unsigned al2 = *(const unsigned*)(xq2 + 8);
            unsigned al3 = *(const unsigned*)(xq2 + 8 * LDP + 8);
#pragma unroll
            for (int nb = 0; nb < 16; nb++) {
                const __half* wp = Wh + (nb * 8 + r0) * LDP + ks * 16 + cq * 2;
                unsigned bh0 = *(const unsigned*)wp;
                unsigned bh1 = *(const unsigned*)(wp + 8);
                const __half* wq2 = Wl + (nb * 8 + r0) * LDP + ks * 16 + cq * 2;
                unsigned bl0 = *(const unsigned*)wq2;
                unsigned bl1 = *(const unsigned*)(wq2 + 8);
                mma16816(acc[nb], ah0, ah1, ah2, ah3, bh0, bh1);
                mma16816(acc[nb], ah0, ah1, ah2, ah3, bl0, bl1);
                mma16816(acc[nb], al0, al1, al2, al3, bh0, bh1);
            }
        }
    }

    __half* out = which ? g_K : g_Q;
    const int gr0 = row0 + warp * 16 + r0;
#pragma unroll
    for (int nb = 0; nb < 16; nb++) {
        int c = nb * 8 + cq * 2;
        float b0 = bias[c], b1 = bias[c + 1];
        *(__half2*)&out[(size_t)gr0 * MID + c] =
            __halves2half2(__float2half_rn(acc[nb][0] + b0), __float2half_rn(acc[nb][1] + b1));
        *(__half2*)&out[(size_t)(gr0 + 8) * MID + c] =
            __halves2half2(__float2half_rn(acc[nb][2] + b0), __float2half_rn(acc[nb][3] + b1));
    }
}

// ---------------- kernel 2: V' = fix * other, stored transposed fp16 ----------------
__global__ __launch_bounds__(256) void vprep_kernel(const float* __restrict__ other,
                                                    const float* __restrict__ fix) {
    __shared__ __half ts[64][66];
    const int m0 = blockIdx.x * 64;
    const int d0 = blockIdx.y * 64;
    const int tid = threadIdx.x;
#pragma unroll
    for (int i = tid; i < 64 * 64; i += 256) {
        int r = i >> 6, c = i & 63;
        float v = other[(size_t)(m0 + r) * QDIM + d0 + c] * fix[m0 + r];
        ts[c][r] = __float2half_rn(v);
    }
    __syncthreads();
#pragma unroll
    for (int i = tid; i < 64 * 64; i += 256) {
        int rr = i >> 6, cc = i & 63;
        g_Vt[(size_t)(d0 + rr) * M_KV + m0 + cc] = ts[rr][cc];
    }
}

// ---------------- kernel 3: flash attention ----------------
// Q fragments in registers; mask streamed GMEM->regs (never in smem); ex2 softmax.
__global__ __launch_bounds__(256, 1) void flash_kernel(const int* __restrict__ maski,
                                                       float* __restrict__ out) {
    extern __shared__ char smem[];
    const int tid  = threadIdx.x;
    const int lane = tid & 31;
    const int warp = tid >> 5;
    const int kvh  = warp >> 2;    // 0/1: which half of each KV tile
    const int rw   = warp & 3;     // row group (16 rows)
    const int r0   = lane >> 2;    // 0..7
    const int cq   = lane & 3;     // 0..3
    const int q0   = blockIdx.x * BM;

    __half* Qs = (__half*)(smem + OFF_Q);

    // ---- prologue: Q tile + first K/V tile ----
#pragma unroll
    for (int i = 0; i < 4; i++) {
        int idx = tid + i * 256;
        int r = idx >> 4, c = idx & 15;
        cpa16((char*)Qs + r * (LDQ * 2) + c * 16,
              (const char*)g_Q + ((size_t)(q0 + r) * MID) * 2 + c * 16);
    }
    CP_COMMIT;

    auto issue_tile = [&](int it, int st) {
        const int kv0 = it * BN;
        char* kb = smem + (st ? OFF_K1 : OFF_K0);
        char* vb = smem + (st ? OFF_V1 : OFF_V0);
#pragma unroll
        for (int i = 0; i < 4; i++) {                      // K: 64 rows x 256B
            int idx = tid + i * 256;
            int r = idx >> 4, c = idx & 15;
            cpa16(kb + r * (LDK * 2) + c * 16,
                  (const char*)g_K + (size_t)(kv0 + r) * (MID * 2) + c * 16);
        }
#pragma unroll
        for (int i = 0; i < 8; i++) {                      // V^T: 256 rows x 128B
            int idx = tid + i * 256;
            int d = idx >> 3, c = idx & 7;
            cpa16(vb + d * (LDV * 2) + c * 16,
                  (const char*)g_Vt + ((size_t)d * M_KV + kv0) * 2 + c * 16);
        }
    };

    issue_tile(0, 0);
    CP_COMMIT;

    // Q landed (wait_group 1 leaves at most the tile-0 group pending)
    CP_WAIT1;
    __syncthreads();

    // ---- Q fragments -> registers (reused across all 128 tiles) ----
    unsigned qa[8][4];
#pragma unroll
    for (int kt = 0; kt < 8; kt++) {
        const __half* qp = Qs + (rw * 16 + r0) * LDQ + kt * 16 + cq * 2;
        qa[kt][0] = *(const unsigned*)qp;
        qa[kt][1] = *(const unsigned*)(qp + 8 * LDQ);
        qa[kt][2] = *(const unsigned*)(qp + 8);
        qa[kt][3] = *(const unsigned*)(qp + 8 * LDQ + 8);
    }

    // ---- mask base pointers + prefetch tile 0 into regs ----
    const int* mb0 = maski + (size_t)(q0 + rw * 16 + r0) * M_KV + kvh * 32 + cq * 2;
    const int* mb1 = mb0 + 8 * (size_t)M_KV;
    int2 mr[8];
#pragma unroll
    for (int nb = 0; nb < 4; nb++) {
        mr[nb]     = *(const int2*)(mb0 + nb * 8);
        mr[4 + nb] = *(const int2*)(mb1 + nb * 8);
    }

    float l0 = 0.f, l1 = 0.f;
    float oacc[32][4];
#pragma unroll
    for (int nb = 0; nb < 32; nb++)
#pragma unroll
        for (int i = 0; i < 4; i++) oacc[nb][i] = 0.f;

    for (int it = 0; it < NIT; it++) {
        const int cur = it & 1;
        if (it + 1 < NIT) {
            issue_tile(it + 1, cur ^ 1);
            CP_COMMIT;
            CP_WAIT1;
        } else {
            CP_WAIT0;
        }
        __syncthreads();

        const __half* Ks = (const __half*)(smem + (cur ? OFF_K1 : OFF_K0));
        const __half* Vs = (const __half*)(smem + (cur ? OFF_V1 : OFF_V0));

        // ---- S = Q K^T (Q from registers) ----
        float sacc[4][4];
#pragma unroll
        for (int nb = 0; nb < 4; nb++)
#pragma unroll
            for (int i = 0; i < 4; i++) sacc[nb][i] = 0.f;

#pragma unroll
        for (int kt = 0; kt < 8; kt++) {
#pragma unroll
            for (int nb = 0; nb < 4; nb++) {
                const __half* kp = Ks + (kvh * 32 + nb * 8 + r0) * LDK + kt * 16 + cq * 2;
                unsigned b0 = *(const unsigned*)kp;
                unsigned b1 = *(const unsigned*)(kp + 8);
                mma16816(sacc[nb], qa[kt][0], qa[kt][1], qa[kt][2], qa[kt][3], b0, b1);
            }
        }

        // ---- mask (from regs) + fixed-shift exp2 ----
#pragma unroll
        for (int nb = 0; nb < 4; nb++) {
            float v0 = mr[nb].x     ? -1e30f : fmaf(sacc[nb][0], SC2, -SH2);
            float v1 = mr[nb].y     ? -1e30f : fmaf(sacc[nb][1], SC2, -SH2);
            float v2 = mr[4 + nb].x ? -1e30f : fmaf(sacc[nb][2], SC2, -SH2);
            float v3 = mr[4 + nb].y ? -1e30f : fmaf(sacc[nb][3], SC2, -SH2);
            float e0 = ex2f(v0), e1 = ex2f(v1), e2 = ex2f(v2), e3 = ex2f(v3);
            sacc[nb][0] = e0; sacc[nb][1] = e1; sacc[nb][2] = e2; sacc[nb][3] = e3;
            l0 += e0 + e1;
            l1 += e2 + e3;
        }

        // ---- prefetch mask for tile it+1 (hidden under PV + next QKT) ----
        if (it + 1 < NIT) {
            const int off = (it + 1) * BN;
#pragma unroll
            for (int nb = 0; nb < 4; nb++) {
                mr[nb]     = *(const int2*)(mb0 + off + nb * 8);
                mr[4 + nb] = *(const int2*)(mb1 + off + nb * 8);
            }
        }

        // ---- O += P V ----
#pragma unroll
        for (int kk = 0; kk < 2; kk++) {
            unsigned pa0 = pack2(sacc[2 * kk][0],     sacc[2 * kk][1]);
            unsigned pa1 = pack2(sacc[2 * kk][2],     sacc[2 * kk][3]);
            unsigned pa2 = pack2(sacc[2 * kk + 1][0], sacc[2 * kk + 1][1]);
            unsigned pa3 = pack2(sacc[2 * kk + 1][2], sacc[2 * kk + 1][3]);
#pragma unroll
            for (int nb = 0; nb < 32; nb++) {
                const __half* vp = Vs + (nb * 8 + r0) * LDV + kvh * 32 + kk * 16 + cq * 2;
                unsigned b0 = *(const unsigned*)vp;
                unsigned b1 = *(const unsigned*)(vp + 8);
                mma16816(oacc[nb], pa0, pa1, pa2, pa3, b0, b1);
            }
        }
        __syncthreads();
    }

    // ---- epilogue: combine KV halves via smem, divide by l, write fp32 ----
    l0 += __shfl_xor_sync(0xffffffffu, l0, 1);
    l0 += __shfl_xor_sync(0xffffffffu, l0, 2);
    l1 += __shfl_xor_sync(0xffffffffu, l1, 1);
    l1 += __shfl_xor_sync(0xffffffffu, l1, 2);

    float* So = (float*)smem;                       // [64][SO_LD]
    float* Sl = (float*)(smem + 64 * SO_LD * 4);    // [64]
    const int rbase = rw * 16;

    if (kvh == 1) {
#pragma unroll
        for (int nb = 0; nb < 32; nb++) {
            int col = nb * 8 + cq * 2;
            *(float2*)&So[(rbase + r0) * SO_LD + col]     = make_float2(oacc[nb][0], oacc[nb][1]);
            *(float2*)&So[(rbase + r0 + 8) * SO_LD + col] = make_float2(oacc[nb][2], oacc[nb][3]);
        }
        if (cq == 0) { Sl[rbase + r0] = l0; Sl[rbase + r0 + 8] = l1; }
    }
    __syncthreads();
    if (kvh == 0) {
        const float il0 = 1.f / (l0 + Sl[rbase + r0]);
        const float il1 = 1.f / (l1 + Sl[rbase + r0 + 8]);
        const int gr0 = q0 + rbase + r0;
        const int gr1 = gr0 + 8;
#pragma unroll
        for (int nb = 0; nb < 32; nb++) {
            int col = nb * 8 + cq * 2;
            float2 ob0 = *(float2*)&So[(rbase + r0) * SO_LD + col];
            float2 ob1 = *(float2*)&So[(rbase + r0 + 8) * SO_LD + col];
            float2 v0 = make_float2((oacc[nb][0] + ob0.x) * il0, (oacc[nb][1] + ob0.y) * il0);
            float2 v1 = make_float2((oacc[nb][2] + ob1.x) * il1, (oacc[nb][3] + ob1.y) * il1);
            *(float2*)(out + (size_t)gr0 * DV + col) = v0;
            *(float2*)(out + (size_t)gr1 * DV + col) = v1;
        }
    }
}

// ---------------- launch ----------------
extern "C" void kernel_launch(void* const* d_in, const int* in_sizes, int n_in,
                              void* d_out, int out_size) {
    const float* mainf  = (const float*)d_in[0];
    const float* otherf = (const float*)d_in[1];
    const float* fixf   = (const float*)d_in[2];
    const int*   mask   = (const int*)d_in[3];   // bool materialized as int32
    const float* Wq = (const float*)d_in[4];
    const float* bq = (const float*)d_in[5];
    const float* Wk = (const float*)d_in[6];
    const float* bk = (const float*)d_in[7];
    float* out = (float*)d_out;

    projmma_kernel<<<128, 256>>>(mainf, otherf, Wq, bq, Wk, bk);
    vprep_kernel<<<dim3(128, 4), 256>>>(otherf, fixf);

    cudaFuncSetAttribute(flash_kernel, cudaFuncAttributeMaxDynamicSharedMemorySize, SMEM_BYTES);
    flash_kernel<<<128, 256, SMEM_BYTES>>>(mask, out);
}

// round 13
// speedup vs baseline: 1.1735x; 1.1735x over previous
#include <cuda_runtime.h>
#include <cuda_fp16.h>
#include <cstdint>
#include <cstddef>

// Problem constants
#define N_Q   8192
#define M_KV  8192
#define QDIM  256
#define MID   128
#define DV    256
#define BM    64
#define BN    64
#define NIT   (M_KV / BN)   // 128
// exp folded to ex2: e^(s*SCALE - SHIFT) = 2^(s*SC2 - SH2)
#define SC2 (0.08838834764831845f * 1.4426950408889634f)
#define SH2 (8.0f * 1.4426950408889634f)

// Scratch (device globals; no allocation allowed)
__device__ __half g_Q[N_Q * MID];      // fp16 Q  [8192][128]
__device__ __half g_K[M_KV * MID];     // fp16 K  [8192][128]
__device__ __half g_Vt[DV * M_KV];     // fp16 V^T [256][8192]

// ---------------- smem geometry for flash kernel (bytes) ----------------
#define LDQ 136
#define LDK 136
#define LDV 72
#define OFF_Q  0
#define OFF_K0 17408
#define OFF_K1 34816
#define OFF_V0 52224
#define OFF_V1 89088
#define SMEM_BYTES 125952
#define SO_LD 260        // float stride for O-partial exchange [64][260]

// ---------------- helpers ----------------
__device__ __forceinline__ void cpa16(void* dst, const void* src) {
    unsigned s = (unsigned)__cvta_generic_to_shared(dst);
    asm volatile("cp.async.cg.shared.global [%0], [%1], 16;\n" :: "r"(s), "l"(src));
}
#define CP_COMMIT asm volatile("cp.async.commit_group;\n" ::)
#define CP_WAIT1  asm volatile("cp.async.wait_group 1;\n" ::)
#define CP_WAIT0  asm volatile("cp.async.wait_group 0;\n" ::)

__device__ __forceinline__ void mma16816(float c[4],
                                         unsigned a0, unsigned a1, unsigned a2, unsigned a3,
                                         unsigned b0, unsigned b1) {
    asm volatile(
        "mma.sync.aligned.m16n8k16.row.col.f32.f16.f16.f32 "
        "{%0,%1,%2,%3}, {%4,%5,%6,%7}, {%8,%9}, {%0,%1,%2,%3};\n"
        : "+f"(c[0]), "+f"(c[1]), "+f"(c[2]), "+f"(c[3])
        : "r"(a0), "r"(a1), "r"(a2), "r"(a3), "r"(b0), "r"(b1));
}

__device__ __forceinline__ unsigned pack2(float a, float b) {
    __half2 h = __floats2half2_rn(a, b);
    return *reinterpret_cast<unsigned*>(&h);
}

__device__ __forceinline__ float ex2f(float x) {
    float y;
    asm("ex2.approx.f32 %0, %1;" : "=f"(y) : "f"(x));
    return y;
}

// ---------------- kernel 1: projections via split-fp16 tensor cores ----------------
#define LDP 40   // smem row stride in halves (80B): conflict-free fragment loads
__global__ __launch_bounds__(256) void projmma_kernel(const float* __restrict__ Xq,
                                                      const float* __restrict__ Xk,
                                                      const float* __restrict__ Wq,
                                                      const float* __restrict__ bq,
                                                      const float* __restrict__ Wk,
                                                      const float* __restrict__ bk) {
    __shared__ __half Xh[128 * LDP], Xl[128 * LDP], Wh[128 * LDP], Wl[128 * LDP];
    const int b = blockIdx.x;
    const int which = b >> 6;
    const int row0 = (b & 63) * 128;
    const float* X    = which ? Xk : Xq;
    const float* W    = which ? Wk : Wq;
    const float* bias = which ? bk : bq;

    const int tid  = threadIdx.x;
    const int lane = tid & 31;
    const int warp = tid >> 5;
    const int r0   = lane >> 2;
    const int cq   = lane & 3;

    const int srow  = tid >> 1;
    const int scol  = (tid & 1) * 16;

    float acc[16][4];
#pragma unroll
    for (int nb = 0; nb < 16; nb++)
#pragma unroll
        for (int i = 0; i < 4; i++) acc[nb][i] = 0.f;

    float4 xr[4], wr[4];
#pragma unroll
    for (int j = 0; j < 4; j++) {
        xr[j] = *(const float4*)(X + (size_t)(row0 + srow) * QDIM + scol + 4 * j);
        wr[j] = *(const float4*)(W + (size_t)srow * QDIM + scol + 4 * j);
    }

    for (int chunk = 0; chunk < 8; chunk++) {
        __syncthreads();
#pragma unroll
        for (int j = 0; j < 4; j++) {
            const float xv[4] = {xr[j].x, xr[j].y, xr[j].z, xr[j].w};
            const float wv[4] = {wr[j].x, wr[j].y, wr[j].z, wr[j].w};
#pragma unroll
            for (int e = 0; e < 2; e++) {
                int c = scol + 4 * j + 2 * e;
                __half h0 = __float2half_rn(xv[2 * e]);
                __half h1 = __float2half_rn(xv[2 * e + 1]);
                __half l0 = __float2half_rn(xv[2 * e]     - __half2float(h0));
                __half l1 = __float2half_rn(xv[2 * e + 1] - __half2float(h1));
                *(__half2*)&Xh[srow * LDP + c] = __halves2half2(h0, h1);
                *(__half2*)&Xl[srow * LDP + c] = __halves2half2(l0, l1);
                __half g0 = __float2half_rn(wv[2 * e]);
                __half g1 = __float2half_rn(wv[2 * e + 1]);
                __half m0 = __float2half_rn(wv[2 * e]     - __half2float(g0));
                __half m1 = __float2half_rn(wv[2 * e + 1] - __half2float(g1));
                *(__half2*)&Wh[srow * LDP + c] = __halves2half2(g0, g1);
                *(__half2*)&Wl[srow * LDP + c] = __halves2half2(m0, m1);
            }
        }
        __syncthreads();
        if (chunk + 1 < 8) {
            int k0 = (chunk + 1) * 32;
#pragma unroll
            for (int j = 0; j < 4; j++) {
                xr[j] = *(const float4*)(X + (size_t)(row0 + srow) * QDIM + k0 + scol + 4 * j);
                wr[j] = *(const float4*)(W + (size_t)srow * QDIM + k0 + scol + 4 * j);
            }
        }
#pragma unroll
        for (int ks = 0; ks < 2; ks++) {
            const __half* xp = Xh + (warp * 16 + r0) * LDP + ks * 16 + cq * 2;
            unsigned ah0 = *(const unsigned*)xp;
            unsigned ah1 = *(const unsigned*)(xp + 8 * LDP);
            unsigned ah2 = *(const unsigned*)(xp + 8);
            unsigned ah3 = *(const unsigned*)(xp + 8 * LDP + 8);
            const __half* xq2 = Xl + (warp * 16 + r0) * LDP + ks * 16 + cq * 2;
            unsigned al0 = *(const unsigned*)xq2;
            unsigned al1 = *(const unsigned*)(xq2 + 8 * LDP);
            unsigned al2 = *(const unsigned*)(xq2 + 8);
            unsigned al3 = *(const unsigned*)(xq2 + 8 * LDP + 8);
#pragma unroll
            for (int nb = 0; nb < 16; nb++) {
                const __half* wp = Wh + (nb * 8 + r0) * LDP + ks * 16 + cq * 2;
                unsigned bh0 = *(const unsigned*)wp;
                unsigned bh1 = *(const unsigned*)(wp + 8);
                const __half* wq2 = Wl + (nb * 8 + r0) * LDP + ks * 16 + cq * 2;
                unsigned bl0 = *(const unsigned*)wq2;
                unsigned bl1 = *(const unsigned*)(wq2 + 8);
                mma16816(acc[nb], ah0, ah1, ah2, ah3, bh0, bh1);
                mma16816(acc[nb], ah0, ah1, ah2, ah3, bl0, bl1);
                mma16816(acc[nb], al0, al1, al2, al3, bh0, bh1);
            }
        }
    }

    __half* out = which ? g_K : g_Q;
    const int gr0 = row0 + warp * 16 + r0;
#pragma unroll
    for (int nb = 0; nb < 16; nb++) {
        int c = nb * 8 + cq * 2;
        float b0 = bias[c], b1 = bias[c + 1];
        *(__half2*)&out[(size_t)gr0 * MID + c] =
            __halves2half2(__float2half_rn(acc[nb][0] + b0), __float2half_rn(acc[nb][1] + b1));
        *(__half2*)&out[(size_t)(gr0 + 8) * MID + c] =
            __halves2half2(__float2half_rn(acc[nb][2] + b0), __float2half_rn(acc[nb][3] + b1));
    }
}

// ---------------- kernel 2: V' = fix * other, stored transposed fp16 ----------------
__global__ __launch_bounds__(256) void vprep_kernel(const float* __restrict__ other,
                                                    const float* __restrict__ fix) {
    __shared__ __half ts[64][66];
    const int m0 = blockIdx.x * 64;
    const int d0 = blockIdx.y * 64;
    const int tid = threadIdx.x;
#pragma unroll
    for (int i = tid; i < 64 * 64; i += 256) {
        int r = i >> 6, c = i & 63;
        float v = other[(size_t)(m0 + r) * QDIM + d0 + c] * fix[m0 + r];
        ts[c][r] = __float2half_rn(v);
    }
    __syncthreads();
#pragma unroll
    for (int i = tid; i < 64 * 64; i += 256) {
        int rr = i >> 6, cc = i & 63;
        g_Vt[(size_t)(d0 + rr) * M_KV + m0 + cc] = ts[rr][cc];
    }
}

// ---------------- kernel 3: flash attention ----------------
// Q/K/V fragments from smem (R8 layout); mask streamed GMEM->regs with a short
// live range (issued at loop top, consumed after QKT, dead during PV); ex2 softmax.
__global__ __launch_bounds__(256, 1) void flash_kernel(const int* __restrict__ maski,
                                                       float* __restrict__ out) {
    extern __shared__ char smem[];
    const int tid  = threadIdx.x;
    const int lane = tid & 31;
    const int warp = tid >> 5;
    const int kvh  = warp >> 2;    // 0/1: which half of each KV tile
    const int rw   = warp & 3;     // row group (16 rows)
    const int r0   = lane >> 2;    // 0..7
    const int cq   = lane & 3;     // 0..3
    const int q0   = blockIdx.x * BM;

    __half* Qs = (__half*)(smem + OFF_Q);

    // ---- prologue: Q tile + first K/V tile ----
#pragma unroll
    for (int i = 0; i < 4; i++) {
        int idx = tid + i * 256;
        int r = idx >> 4, c = idx & 15;
        cpa16((char*)Qs + r * (LDQ * 2) + c * 16,
              (const char*)g_Q + ((size_t)(q0 + r) * MID) * 2 + c * 16);
    }
    CP_COMMIT;

    auto issue_tile = [&](int it, int st) {
        const int kv0 = it * BN;
        char* kb = smem + (st ? OFF_K1 : OFF_K0);
        char* vb = smem + (st ? OFF_V1 : OFF_V0);
#pragma unroll
        for (int i = 0; i < 4; i++) {                      // K: 64 rows x 256B
            int idx = tid + i * 256;
            int r = idx >> 4, c = idx & 15;
            cpa16(kb + r * (LDK * 2) + c * 16,
                  (const char*)g_K + (size_t)(kv0 + r) * (MID * 2) + c * 16);
        }
#pragma unroll
        for (int i = 0; i < 8; i++) {                      // V^T: 256 rows x 128B
            int idx = tid + i * 256;
            int d = idx >> 3, c = idx & 7;
            cpa16(vb + d * (LDV * 2) + c * 16,
                  (const char*)g_Vt + ((size_t)d * M_KV + kv0) * 2 + c * 16);
        }
    };

    issue_tile(0, 0);
    CP_COMMIT;

    // mask base pointers for this thread's rows
    const int* mb0 = maski + (size_t)(q0 + rw * 16 + r0) * M_KV + kvh * 32 + cq * 2;
    const int* mb1 = mb0 + 8 * (size_t)M_KV;

    float l0 = 0.f, l1 = 0.f;
    float oacc[32][4];
#pragma unroll
    for (int nb = 0; nb < 32; nb++)
#pragma unroll
        for (int i = 0; i < 4; i++) oacc[nb][i] = 0.f;

    for (int it = 0; it < NIT; it++) {
        const int cur = it & 1;
        if (it + 1 < NIT) {
            issue_tile(it + 1, cur ^ 1);
            CP_COMMIT;
            CP_WAIT1;
        } else {
            CP_WAIT0;
        }
        __syncthreads();

        const __half* Ks = (const __half*)(smem + (cur ? OFF_K1 : OFF_K0));
        const __half* Vs = (const __half*)(smem + (cur ? OFF_V1 : OFF_V0));

        // ---- issue mask loads for THIS tile (latency hidden under QKT MMAs) ----
        const int moff = it * BN;
        int2 mr[8];
#pragma unroll
        for (int nb = 0; nb < 4; nb++) {
            mr[nb]     = __ldg((const int2*)(mb0 + moff + nb * 8));
            mr[4 + nb] = __ldg((const int2*)(mb1 + moff + nb * 8));
        }

        // ---- S = Q K^T ----
        float sacc[4][4];
#pragma unroll
        for (int nb = 0; nb < 4; nb++)
#pragma unroll
            for (int i = 0; i < 4; i++) sacc[nb][i] = 0.f;

#pragma unroll
        for (int kt = 0; kt < 8; kt++) {
            const __half* qp = Qs + (rw * 16 + r0) * LDQ + kt * 16 + cq * 2;
            unsigned a0 = *(const unsigned*)qp;
            unsigned a1 = *(const unsigned*)(qp + 8 * LDQ);
            unsigned a2 = *(const unsigned*)(qp + 8);
            unsigned a3 = *(const unsigned*)(qp + 8 * LDQ + 8);
#pragma unroll
            for (int nb = 0; nb < 4; nb++) {
                const __half* kp = Ks + (kvh * 32 + nb * 8 + r0) * LDK + kt * 16 + cq * 2;
                unsigned b0 = *(const unsigned*)kp;
                unsigned b1 = *(const unsigned*)(kp + 8);
                mma16816(sacc[nb], a0, a1, a2, a3, b0, b1);
            }
        }

        // ---- mask (regs) + fixed-shift exp2 ----
#pragma unroll
        for (int nb = 0; nb < 4; nb++) {
            float v0 = mr[nb].x     ? -1e30f : fmaf(sacc[nb][0], SC2, -SH2);
            float v1 = mr[nb].y     ? -1e30f : fmaf(sacc[nb][1], SC2, -SH2);
            float v2 = mr[4 + nb].x ? -1e30f : fmaf(sacc[nb][2], SC2, -SH2);
            float v3 = mr[4 + nb].y ? -1e30f : fmaf(sacc[nb][3], SC2, -SH2);
            float e0 = ex2f(v0), e1 = ex2f(v1), e2 = ex2f(v2), e3 = ex2f(v3);
            sacc[nb][0] = e0; sacc[nb][1] = e1; sacc[nb][2] = e2; sacc[nb][3] = e3;
            l0 += e0 + e1;
            l1 += e2 + e3;
        }

        // ---- O += P V ----
#pragma unroll
        for (int kk = 0; kk < 2; kk++) {
            unsigned pa0 = pack2(sacc[2 * kk][0],     sacc[2 * kk][1]);
            unsigned pa1 = pack2(sacc[2 * kk][2],     sacc[2 * kk][3]);
            unsigned pa2 = pack2(sacc[2 * kk + 1][0], sacc[2 * kk + 1][1]);
            unsigned pa3 = pack2(sacc[2 * kk + 1][2], sacc[2 * kk + 1][3]);
#pragma unroll
            for (int nb = 0; nb < 32; nb++) {
                const __half* vp = Vs + (nb * 8 + r0) * LDV + kvh * 32 + kk * 16 + cq * 2;
                unsigned b0 = *(const unsigned*)vp;
                unsigned b1 = *(const unsigned*)(vp + 8);
                mma16816(oacc[nb], pa0, pa1, pa2, pa3, b0, b1);
            }
        }
        __syncthreads();
    }

    // ---- epilogue: combine KV halves via smem, divide by l, write fp32 ----
    l0 += __shfl_xor_sync(0xffffffffu, l0, 1);
    l0 += __shfl_xor_sync(0xffffffffu, l0, 2);
    l1 += __shfl_xor_sync(0xffffffffu, l1, 1);
    l1 += __shfl_xor_sync(0xffffffffu, l1, 2);

    float* So = (float*)smem;                       // [64][SO_LD]
    float* Sl = (float*)(smem + 64 * SO_LD * 4);    // [64]
    const int rbase = rw * 16;

    if (kvh == 1) {
#pragma unroll
        for (int nb = 0; nb < 32; nb++) {
            int col = nb * 8 + cq * 2;
            *(float2*)&So[(rbase + r0) * SO_LD + col]     = make_float2(oacc[nb][0], oacc[nb][1]);
            *(float2*)&So[(rbase + r0 + 8) * SO_LD + col] = make_float2(oacc[nb][2], oacc[nb][3]);
        }
        if (cq == 0) { Sl[rbase + r0] = l0; Sl[rbase + r0 + 8] = l1; }
    }
    __syncthreads();
    if (kvh == 0) {
        const float il0 = 1.f / (l0 + Sl[rbase + r0]);
        const float il1 = 1.f / (l1 + Sl[rbase + r0 + 8]);
        const int gr0 = q0 + rbase + r0;
        const int gr1 = gr0 + 8;
#pragma unroll
        for (int nb = 0; nb < 32; nb++) {
            int col = nb * 8 + cq * 2;
            float2 ob0 = *(float2*)&So[(rbase + r0) * SO_LD + col];
            float2 ob1 = *(float2*)&So[(rbase + r0 + 8) * SO_LD + col];
            float2 v0 = make_float2((oacc[nb][0] + ob0.x) * il0, (oacc[nb][1] + ob0.y) * il0);
            float2 v1 = make_float2((oacc[nb][2] + ob1.x) * il1, (oacc[nb][3] + ob1.y) * il1);
            *(float2*)(out + (size_t)gr0 * DV + col) = v0;
            *(float2*)(out + (size_t)gr1 * DV + col) = v1;
        }
    }
}

// ---------------- launch ----------------
extern "C" void kernel_launch(void* const* d_in, const int* in_sizes, int n_in,
                              void* d_out, int out_size) {
    const float* mainf  = (const float*)d_in[0];
    const float* otherf = (const float*)d_in[1];
    const float* fixf   = (const float*)d_in[2];
    const int*   mask   = (const int*)d_in[3];   // bool materialized as int32
    const float* Wq = (const float*)d_in[4];
    const float* bq = (const float*)d_in[5];
    const float* Wk = (const float*)d_in[6];
    const float* bk = (const float*)d_in[7];
    float* out = (float*)d_out;

    projmma_kernel<<<128, 256>>>(mainf, otherf, Wq, bq, Wk, bk);
    vprep_kernel<<<dim3(128, 4), 256>>>(otherf, fixf);

    cudaFuncSetAttribute(flash_kernel, cudaFuncAttributeMaxDynamicSharedMemorySize, SMEM_BYTES);
    flash_kernel<<<128, 256, SMEM_BYTES>>>(mask, out);
}

// round 17
// speedup vs baseline: 1.2579x; 1.0719x over previous
#include <cuda_runtime.h>
#include <cuda_fp16.h>
#include <cstdint>
#include <cstddef>

// Problem constants
#define N_Q   8192
#define M_KV  8192
#define QDIM  256
#define MID   128
#define DV    256
#define BM    64
#define BN    64
#define NIT   (M_KV / BN)   // 128
// exp folded to ex2: e^(s*SCALE - SHIFT) = 2^(s*SC2 - SH2)
#define SC2 (0.08838834764831845f * 1.4426950408889634f)
#define SH2 (8.0f * 1.4426950408889634f)

// Scratch (device globals; no allocation allowed)
__device__ __half g_Q[N_Q * MID];      // fp16 Q  [8192][128]
__device__ __half g_K[M_KV * MID];     // fp16 K  [8192][128]
__device__ __half g_Vt[DV * M_KV];     // fp16 V^T [256][8192]

// ---------------- smem geometry for flash kernel (bytes) ----------------
#define LDQ 136
#define LDK 136
#define LDV 72
#define OFF_Q  0
#define OFF_K0 17408
#define OFF_K1 34816
#define OFF_V0 52224
#define OFF_V1 89088
#define SM_MB0 125952      // packed mask tile: 64 rows x 8B = 512B
#define SM_MB1 126464
#define SMEM_BYTES 126976
#define SO_LD 260          // float stride for O-partial exchange [64][260]

// ---------------- helpers ----------------
__device__ __forceinline__ void cpa16(void* dst, const void* src) {
    unsigned s = (unsigned)__cvta_generic_to_shared(dst);
    asm volatile("cp.async.cg.shared.global [%0], [%1], 16;\n" :: "r"(s), "l"(src));
}
#define CP_COMMIT asm volatile("cp.async.commit_group;\n" ::)
#define CP_WAIT1  asm volatile("cp.async.wait_group 1;\n" ::)
#define CP_WAIT0  asm volatile("cp.async.wait_group 0;\n" ::)

__device__ __forceinline__ void mma16816(float c[4],
                                         unsigned a0, unsigned a1, unsigned a2, unsigned a3,
                                         unsigned b0, unsigned b1) {
    asm volatile(
        "mma.sync.aligned.m16n8k16.row.col.f32.f16.f16.f32 "
        "{%0,%1,%2,%3}, {%4,%5,%6,%7}, {%8,%9}, {%0,%1,%2,%3};\n"
        : "+f"(c[0]), "+f"(c[1]), "+f"(c[2]), "+f"(c[3])
        : "r"(a0), "r"(a1), "r"(a2), "r"(a3), "r"(b0), "r"(b1));
}

__device__ __forceinline__ unsigned pack2(float a, float b) {
    __half2 h = __floats2half2_rn(a, b);
    return *reinterpret_cast<unsigned*>(&h);
}

__device__ __forceinline__ float ex2f(float x) {
    float y;
    asm("ex2.approx.f32 %0, %1;" : "=f"(y) : "f"(x));
    return y;
}

// ---------------- kernel 1: projections via split-fp16 tensor cores ----------------
#define LDP 40   // smem row stride in halves (80B): conflict-free fragment loads
__global__ __launch_bounds__(256) void projmma_kernel(const float* __restrict__ Xq,
                                                      const float* __restrict__ Xk,
                                                      const float* __restrict__ Wq,
                                                      const float* __restrict__ bq,
                                                      const float* __restrict__ Wk,
                                                      const float* __restrict__ bk) {
    __shared__ __half Xh[128 * LDP], Xl[128 * LDP], Wh[128 * LDP], Wl[128 * LDP];
    const int b = blockIdx.x;
    const int which = b >> 6;
    const int row0 = (b & 63) * 128;
    const float* X    = which ? Xk : Xq;
    const float* W    = which ? Wk : Wq;
    const float* bias = which ? bk : bq;

    const int tid  = threadIdx.x;
    const int lane = tid & 31;
    const int warp = tid >> 5;
    const int r0   = lane >> 2;
    const int cq   = lane & 3;

    const int srow  = tid >> 1;
    const int scol  = (tid & 1) * 16;

    float acc[16][4];
#pragma unroll
    for (int nb = 0; nb < 16; nb++)
#pragma unroll
        for (int i = 0; i < 4; i++) acc[nb][i] = 0.f;

    float4 xr[4], wr[4];
#pragma unroll
    for (int j = 0; j < 4; j++) {
        xr[j] = *(const float4*)(X + (size_t)(row0 + srow) * QDIM + scol + 4 * j);
        wr[j] = *(const float4*)(W + (size_t)srow * QDIM + scol + 4 * j);
    }

    for (int chunk = 0; chunk < 8; chunk++) {
        __syncthreads();
#pragma unroll
        for (int j = 0; j < 4; j++) {
            const float xv[4] = {xr[j].x, xr[j].y, xr[j].z, xr[j].w};
            const float wv[4] = {wr[j].x, wr[j].y, wr[j].z, wr[j].w};
#pragma unroll
            for (int e = 0; e < 2; e++) {
                int c = scol + 4 * j + 2 * e;
                __half h0 = __float2half_rn(xv[2 * e]);
                __half h1 = __float2half_rn(xv[2 * e + 1]);
                __half l0 = __float2half_rn(xv[2 * e]     - __half2float(h0));
                __half l1 = __float2half_rn(xv[2 * e + 1] - __half2float(h1));
                *(__half2*)&Xh[srow * LDP + c] = __halves2half2(h0, h1);
                *(__half2*)&Xl[srow * LDP + c] = __halves2half2(l0, l1);
                __half g0 = __float2half_rn(wv[2 * e]);
                __half g1 = __float2half_rn(wv[2 * e + 1]);
                __half m0 = __float2half_rn(wv[2 * e]     - __half2float(g0));
                __half m1 = __float2half_rn(wv[2 * e + 1] - __half2float(g1));
                *(__half2*)&Wh[srow * LDP + c] = __halves2half2(g0, g1);
                *(__half2*)&Wl[srow * LDP + c] = __halves2half2(m0, m1);
            }
        }
        __syncthreads();
        if (chunk + 1 < 8) {
            int k0 = (chunk + 1) * 32;
#pragma unroll
            for (int j = 0; j < 4; j++) {
                xr[j] = *(const float4*)(X + (size_t)(row0 + srow) * QDIM + k0 + scol + 4 * j);
                wr[j] = *(const float4*)(W + (size_t)srow * QDIM + k0 + scol + 4 * j);
            }
        }
#pragma unroll
        for (int ks = 0; ks < 2; ks++) {
            const __half* xp = Xh + (warp * 16 + r0) * LDP + ks * 16 + cq * 2;
            unsigned ah0 = *(const unsigned*)xp;
            unsigned ah1 = *(const unsigned*)(xp + 8 * LDP);
            unsigned ah2 = *(const unsigned*)(xp + 8);
            unsigned ah3 = *(const unsigned*)(xp + 8 * LDP + 8);
            const __half* xq2 = Xl + (warp * 16 + r0) * LDP + ks * 16 + cq * 2;
            unsigned al0 = *(const unsigned*)xq2;
            unsigned al1 = *(const unsigned*)(xq2 + 8 * LDP);
            unsigned al2 = *(const unsigned*)(xq2 + 8);
            unsigned al3 = *(const unsigned*)(xq2 + 8 * LDP + 8);
#pragma unroll
            for (int nb = 0; nb < 16; nb++) {
                const __half* wp = Wh + (nb * 8 + r0) * LDP + ks * 16 + cq * 2;
                unsigned bh0 = *(const unsigned*)wp;
                unsigned bh1 = *(const unsigned*)(wp + 8);
                const __half* wq2 = Wl + (nb * 8 + r0) * LDP + ks * 16 + cq * 2;
                unsigned bl0 = *(const unsigned*)wq2;
                unsigned bl1 = *(const unsigned*)(wq2 + 8);
                mma16816(acc[nb], ah0, ah1, ah2, ah3, bh0, bh1);
                mma16816(acc[nb], ah0, ah1, ah2, ah3, bl0, bl1);
                mma16816(acc[nb], al0, al1, al2, al3, bh0, bh1);
            }
        }
    }

    __half* out = which ? g_K : g_Q;
    const int gr0 = row0 + warp * 16 + r0;
#pragma unroll
    for (int nb = 0; nb < 16; nb++) {
        int c = nb * 8 + cq * 2;
        float b0 = bias[c], b1 = bias[c + 1];
        *(__half2*)&out[(size_t)gr0 * MID + c] =
            __halves2half2(__float2half_rn(acc[nb][0] + b0), __float2half_rn(acc[nb][1] + b1));
        *(__half2*)&out[(size_t)(gr0 + 8) * MID + c] =
            __halves2half2(__float2half_rn(acc[nb][2] + b0), __float2half_rn(acc[nb][3] + b1));
    }
}

// ---------------- kernel 2: V' = fix * other, stored transposed fp16 ----------------
__global__ __launch_bounds__(256) void vprep_kernel(const float* __restrict__ other,
                                                    const float* __restrict__ fix) {
    __shared__ __half ts[64][66];
    const int m0 = blockIdx.x * 64;
    const int d0 = blockIdx.y * 64;
    const int tid = threadIdx.x;
#pragma unroll
    for (int i = tid; i < 64 * 64; i += 256) {
        int r = i >> 6, c = i & 63;
        float v = other[(size_t)(m0 + r) * QDIM + d0 + c] * fix[m0 + r];
        ts[c][r] = __float2half_rn(v);
    }
    __syncthreads();
#pragma unroll
    for (int i = tid; i < 64 * 64; i += 256) {
        int rr = i >> 6, cc = i & 63;
        g_Vt[(size_t)(d0 + rr) * M_KV + m0 + cc] = ts[rr][cc];
    }
}

// ---------------- kernel 3: flash attention ----------------
// Mask bit-packed: coalesced LDG.128 (next tile, issued early) -> 16-bit pack ->
// 512B smem buffer; softmax reads 2 LDS.32/thread + bit extract. K/V via cp.async.
__global__ __launch_bounds__(256, 1) void flash_kernel(const int* __restrict__ maski,
                                                       float* __restrict__ out) {
    extern __shared__ char smem[];
    const int tid  = threadIdx.x;
    const int lane = tid & 31;
    const int warp = tid >> 5;
    const int kvh  = warp >> 2;    // 0/1: which half of each KV tile
    const int rw   = warp & 3;     // row group (16 rows)
    const int r0   = lane >> 2;    // 0..7
    const int cq   = lane & 3;     // 0..3
    const int q0   = blockIdx.x * BM;

    __half* Qs = (__half*)(smem + OFF_Q);

    // mask staging map: thread -> (row, 16-col chunk)
    const int mrow  = tid >> 2;    // 0..63
    const int mchk  = tid & 3;     // 0..3
    const int* mgp  = maski + (size_t)(q0 + mrow) * M_KV + mchk * 16;

    // ---- prologue: Q tile + first K/V tile ----
#pragma unroll
    for (int i = 0; i < 4; i++) {
        int idx = tid + i * 256;
        int r = idx >> 4, c = idx & 15;
        cpa16((char*)Qs + r * (LDQ * 2) + c * 16,
              (const char*)g_Q + ((size_t)(q0 + r) * MID) * 2 + c * 16);
    }
    CP_COMMIT;

    auto issue_tile = [&](int it, int st) {
        const int kv0 = it * BN;
        char* kb = smem + (st ? OFF_K1 : OFF_K0);
        char* vb = smem + (st ? OFF_V1 : OFF_V0);
#pragma unroll
        for (int i = 0; i < 4; i++) {                      // K: 64 rows x 256B
            int idx = tid + i * 256;
            int r = idx >> 4, c = idx & 15;
            cpa16(kb + r * (LDK * 2) + c * 16,
                  (const char*)g_K + (size_t)(kv0 + r) * (MID * 2) + c * 16);
        }
#pragma unroll
        for (int i = 0; i < 8; i++) {                      // V^T: 256 rows x 128B
            int idx = tid + i * 256;
            int d = idx >> 3, c = idx & 7;
            cpa16(vb + d * (LDV * 2) + c * 16,
                  (const char*)g_Vt + ((size_t)d * M_KV + kv0) * 2 + c * 16);
        }
    };

    auto pack_bits = [&](const int4* m4) -> unsigned {
        unsigned b = 0;
#pragma unroll
        for (int j = 0; j < 4; j++) {
            if (m4[j].x) b |= 1u << (4 * j + 0);
            if (m4[j].y) b |= 1u << (4 * j + 1);
            if (m4[j].z) b |= 1u << (4 * j + 2);
            if (m4[j].w) b |= 1u << (4 * j + 3);
        }
        return b;
    };

    issue_tile(0, 0);
    CP_COMMIT;

    // ---- prologue: pack mask tile 0 into SM_MB0 ----
    {
        int4 m4[4];
#pragma unroll
        for (int j = 0; j < 4; j++) m4[j] = __ldg((const int4*)(mgp + 4 * j));
        unsigned b = pack_bits(m4);
        *(unsigned short*)(smem + SM_MB0 + mrow * 8 + mchk * 2) = (unsigned short)b;
    }

    float l0 = 0.f, l1 = 0.f;
    float oacc[32][4];
#pragma unroll
    for (int nb = 0; nb < 32; nb++)
#pragma unroll
        for (int i = 0; i < 4; i++) oacc[nb][i] = 0.f;

    const int msb = 2 * cq;   // bit shift base for this thread's columns

    for (int it = 0; it < NIT; it++) {
        const int cur = it & 1;

        // ---- issue coalesced mask LDGs for tile it+1 (packed after softmax) ----
        int4 nm[4];
        if (it + 1 < NIT) {
            const int* p = mgp + (it + 1) * BN;
#pragma unroll
            for (int j = 0; j < 4; j++) nm[j] = __ldg((const int4*)(p + 4 * j));
        }

        if (it + 1 < NIT) {
            issue_tile(it + 1, cur ^ 1);
            CP_COMMIT;
            CP_WAIT1;
        } else {
            CP_WAIT0;
        }
        __syncthreads();

        const __half* Ks = (const __half*)(smem + (cur ? OFF_K1 : OFF_K0));
        const __half* Vs = (const __half*)(smem + (cur ? OFF_V1 : OFF_V0));

        // ---- S = Q K^T ----
        float sacc[4][4];
#pragma unroll
        for (int nb = 0; nb < 4; nb++)
#pragma unroll
            for (int i = 0; i < 4; i++) sacc[nb][i] = 0.f;

#pragma unroll
        for (int kt = 0; kt < 8; kt++) {
            const __half* qp = Qs + (rw * 16 + r0) * LDQ + kt * 16 + cq * 2;
            unsigned a0 = *(const unsigned*)qp;
            unsigned a1 = *(const unsigned*)(qp + 8 * LDQ);
            unsigned a2 = *(const unsigned*)(qp + 8);
            unsigned a3 = *(const unsigned*)(qp + 8 * LDQ + 8);
#pragma unroll
            for (int nb = 0; nb < 4; nb++) {
                const __half* kp = Ks + (kvh * 32 + nb * 8 + r0) * LDK + kt * 16 + cq * 2;
                unsigned b0 = *(const unsigned*)kp;
                unsigned b1 = *(const unsigned*)(kp + 8);
                mma16816(sacc[nb], a0, a1, a2, a3, b0, b1);
            }
        }

        // ---- mask bits (2 LDS.32, multicast) + fixed-shift exp2 ----
        const char* mbuf = smem + (cur ? SM_MB1 : SM_MB0);
        const unsigned w0 = *(const unsigned*)(mbuf + (rw * 16 + r0) * 8 + kvh * 4);
        const unsigned w1 = *(const unsigned*)(mbuf + (rw * 16 + r0 + 8) * 8 + kvh * 4);
#pragma unroll
        for (int nb = 0; nb < 4; nb++) {
            float v0 = ((w0 >> (msb + 8 * nb)) & 1u)     ? -1e30f : fmaf(sacc[nb][0], SC2, -SH2);
            float v1 = ((w0 >> (msb + 8 * nb + 1)) & 1u) ? -1e30f : fmaf(sacc[nb][1], SC2, -SH2);
            float v2 = ((w1 >> (msb + 8 * nb)) & 1u)     ? -1e30f : fmaf(sacc[nb][2], SC2, -SH2);
            float v3 = ((w1 >> (msb + 8 * nb + 1)) & 1u) ? -1e30f : fmaf(sacc[nb][3], SC2, -SH2);
            float e0 = ex2f(v0), e1 = ex2f(v1), e2 = ex2f(v2), e3 = ex2f(v3);
            sacc[nb][0] = e0; sacc[nb][1] = e1; sacc[nb][2] = e2; sacc[nb][3] = e3;
            l0 += e0 + e1;
            l1 += e2 + e3;
        }

        // ---- pack + store next tile's mask bits (ordered by end-of-iter sync) ----
        if (it + 1 < NIT) {
            unsigned b = pack_bits(nm);
            *(unsigned short*)(smem + ((cur ^ 1) ? SM_MB1 : SM_MB0) + mrow * 8 + mchk * 2)
                = (unsigned short)b;
        }

        // ---- O += P V ----
#pragma unroll
        for (int kk = 0; kk < 2; kk++) {
            unsigned pa0 = pack2(sacc[2 * kk][0],     sacc[2 * kk][1]);
            unsigned pa1 = pack2(sacc[2 * kk][2],     sacc[2 * kk][3]);
            unsigned pa2 = pack2(sacc[2 * kk + 1][0], sacc[2 * kk + 1][1]);
            unsigned pa3 = pack2(sacc[2 * kk + 1][2], sacc[2 * kk + 1][3]);
#pragma unroll
            for (int nb = 0; nb < 32; nb++) {
                const __half* vp = Vs + (nb * 8 + r0) * LDV + kvh * 32 + kk * 16 + cq * 2;
                unsigned b0 = *(const unsigned*)vp;
                unsigned b1 = *(const unsigned*)(vp + 8);
                mma16816(oacc[nb], pa0, pa1, pa2, pa3, b0, b1);
            }
        }
        __syncthreads();
    }

    // ---- epilogue: combine KV halves via smem, divide by l, write fp32 ----
    l0 += __shfl_xor_sync(0xffffffffu, l0, 1);
    l0 += __shfl_xor_sync(0xffffffffu, l0, 2);
    l1 += __shfl_xor_sync(0xffffffffu, l1, 1);
    l1 += __shfl_xor_sync(0xffffffffu, l1, 2);

    float* So = (float*)smem;                       // [64][SO_LD]
    float* Sl = (float*)(smem + 64 * SO_LD * 4);    // [64]
    const int rbase = rw * 16;

    if (kvh == 1) {
#pragma unroll
        for (int nb = 0; nb < 32; nb++) {
            int col = nb * 8 + cq * 2;
            *(float2*)&So[(rbase + r0) * SO_LD + col]     = make_float2(oacc[nb][0], oacc[nb][1]);
            *(float2*)&So[(rbase + r0 + 8) * SO_LD + col] = make_float2(oacc[nb][2], oacc[nb][3]);
        }
        if (cq == 0) { Sl[rbase + r0] = l0; Sl[rbase + r0 + 8] = l1; }
    }
    __syncthreads();
    if (kvh == 0) {
        const float il0 = 1.f / (l0 + Sl[rbase + r0]);
        const float il1 = 1.f / (l1 + Sl[rbase + r0 + 8]);
        const int gr0 = q0 + rbase + r0;
        const int gr1 = gr0 + 8;
#pragma unroll
        for (int nb = 0; nb < 32; nb++) {
            int col = nb * 8 + cq * 2;
            float2 ob0 = *(float2*)&So[(rbase + r0) * SO_LD + col];
            float2 ob1 = *(float2*)&So[(rbase + r0 + 8) * SO_LD + col];
            float2 v0 = make_float2((oacc[nb][0] + ob0.x) * il0, (oacc[nb][1] + ob0.y) * il0);
            float2 v1 = make_float2((oacc[nb][2] + ob1.x) * il1, (oacc[nb][3] + ob1.y) * il1);
            *(float2*)(out + (size_t)gr0 * DV + col) = v0;
            *(float2*)(out + (size_t)gr1 * DV + col) = v1;
        }
    }
}

// ---------------- launch ----------------
extern "C" void kernel_launch(void* const* d_in, const int* in_sizes, int n_in,
                              void* d_out, int out_size) {
    const float* mainf  = (const float*)d_in[0];
    const float* otherf = (const float*)d_in[1];
    const float* fixf   = (const float*)d_in[2];
    const int*   mask   = (const int*)d_in[3];   // bool materialized as int32
    const float* Wq = (const float*)d_in[4];
    const float* bq = (const float*)d_in[5];
    const float* Wk = (const float*)d_in[6];
    const float* bk = (const float*)d_in[7];
    float* out = (float*)d_out;

    projmma_kernel<<<128, 256>>>(mainf, otherf, Wq, bq, Wk, bk);
    vprep_kernel<<<dim3(128, 4), 256>>>(otherf, fixf);

    cudaFuncSetAttribute(flash_kernel, cudaFuncAttributeMaxDynamicSharedMemorySize, SMEM_BYTES);
    flash_kernel<<<128, 256, SMEM_BYTES>>>(mask, out);
}